// round 2
// baseline (speedup 1.0000x reference)
#include <cuda_runtime.h>

// OrbitalAEVComputer: coefficients [64,256,45] f32 -> out [64,256,4608] f32
// Per (conf,atom): 12 AOVs (4 p + 8 reordered d), radial 12*32, angular 66*8*8.

#define NBLOCKS (64 * 256)
#define OUT_STRIDE 4608
#define NPAIR 66

// cos/sin of shfZ = linspace(0.19634954, 2.94524311, 8)  (odd multiples of pi/16)
__constant__ float COSZ[8] = {
     0.98078528f,  0.83146961f,  0.55557023f,  0.19509032f,
    -0.19509032f, -0.55557023f, -0.83146961f, -0.98078528f
};
__constant__ float SINZ[8] = {
     0.19509032f,  0.55557023f,  0.83146961f,  0.98078528f,
     0.98078528f,  0.83146961f,  0.55557023f,  0.19509032f
};

// triu_indices(12, k=1), i-major
__constant__ unsigned char IU[NPAIR] = {
    0,0,0,0,0,0,0,0,0,0,0,
    1,1,1,1,1,1,1,1,1,1,
    2,2,2,2,2,2,2,2,2,
    3,3,3,3,3,3,3,3,
    4,4,4,4,4,4,4,
    5,5,5,5,5,5,
    6,6,6,6,6,
    7,7,7,7,
    8,8,8,
    9,9,
    10
};
__constant__ unsigned char JU[NPAIR] = {
    1,2,3,4,5,6,7,8,9,10,11,
    2,3,4,5,6,7,8,9,10,11,
    3,4,5,6,7,8,9,10,11,
    4,5,6,7,8,9,10,11,
    5,6,7,8,9,10,11,
    6,7,8,9,10,11,
    7,8,9,10,11,
    8,9,10,11,
    9,10,11,
    10,11,
    11
};

__global__ __launch_bounds__(128, 10)
void orbital_aev_kernel(const float* __restrict__ coeff, float* __restrict__ out)
{
    __shared__ float  dsh[12];
    __shared__ float  nvsh[12][3];
    __shared__ float2 czsz[NPAIR];          // (0.95*cos, sin-of-acos)
    __shared__ float  f2sh[NPAIR][8];       // factor2 table, 32B per pair row

    const int t = threadIdx.x;
    const float* __restrict__ c = coeff + (size_t)blockIdx.x * 45;
    float* __restrict__ o = out + (size_t)blockIdx.x * OUT_STRIDE;

    // ---- Build 12 AOVs: dist + normalized vectors into SMEM ----
    if (t < 12) {
        float x, y, z;
        if (t < 4) {
            int b = 9 + 3 * t;
            x = c[b]; y = c[b + 1]; z = c[b + 2];
        } else {
            int r = (t - 4) >> 1;
            int b = 21 + 6 * r;
            if (((t - 4) & 1) == 0) {        // d row picks [0,2,5]
                x = c[b];     y = c[b + 2]; z = c[b + 5];
            } else {                          // then [4,3,1]
                x = c[b + 4]; y = c[b + 3]; z = c[b + 1];
            }
        }
        float s = x * x + y * y + z * z;
        float inv, d;
        if (s > 1e-24f) { inv = rsqrtf(s); d = s * inv; }
        else            { inv = 0.0f;      d = 0.0f;    }
        dsh[t] = d;
        nvsh[t][0] = x * inv;
        nvsh[t][1] = y * inv;
        nvsh[t][2] = z * inv;
    }
    __syncthreads();

    // ---- Pair angle terms: cz = 0.95*cos(angle), sz = sqrt(1-cz^2) ----
    if (t < NPAIR) {
        int i = IU[t], j = JU[t];
        float cc = nvsh[i][0] * nvsh[j][0]
                 + nvsh[i][1] * nvsh[j][1]
                 + nvsh[i][2] * nvsh[j][2];
        float cz = 0.95f * cc;
        float sz = sqrtf(fmaxf(0.0f, 1.0f - cz * cz));
        czsz[t] = make_float2(cz, sz);
    }

    // ---- Radial: s_aev == r_aev (identical shifts & eta). 384 outputs as 96 STG.128.
    //      thread t<96: aov = t>>3, q = t&7; float4 at column q*4; exp shift k = (q&3)*4+j.
    if (t < 96) {
        int aov = t >> 3;
        int q   = t & 7;
        float d  = dsh[aov];
        int   kb = (q & 3) << 2;
        float u0 = d - (0.5f + 0.2f * (float)(kb + 0));
        float u1 = d - (0.5f + 0.2f * (float)(kb + 1));
        float u2 = d - (0.5f + 0.2f * (float)(kb + 2));
        float u3 = d - (0.5f + 0.2f * (float)(kb + 3));
        float4 v = make_float4(__expf(-16.0f * u0 * u0),
                               __expf(-16.0f * u1 * u1),
                               __expf(-16.0f * u2 * u2),
                               __expf(-16.0f * u3 * u3));
        *reinterpret_cast<float4*>(o + (aov << 5) + (q << 2)) = v;
    }

    // ---- factor2 table: 528 exps. a = m&7 == t&7 is per-thread invariant. ----
    {
        const float aco = 0.5f + (3.0f / 7.0f) * (float)(t & 7);
        #pragma unroll
        for (int m = t; m < 528; m += 128) {
            int p = m >> 3;
            float av = 0.5f * (dsh[IU[p]] + dsh[JU[p]]);
            float ua = av - aco;
            reinterpret_cast<float*>(f2sh)[m] = __expf(-8.0f * ua * ua);
        }
    }
    __syncthreads();

    // ---- Angular store loop: per task (pair p, z = t&7): g = 2*((1+cos(angle-shfZ))/2)^32 ----
    const float cosz = COSZ[t & 7];
    const float sinz = SINZ[t & 7];
    #pragma unroll
    for (int iter = 0; iter < 5; iter++) {
        int m = t + 128 * iter;
        if (m < 528) {
            int p = m >> 3;
            float2 cs = czsz[p];
            float cosd = fmaf(cs.x, cosz, cs.y * sinz);   // cos(angle - shfZ), exact identity
            float b = fmaf(0.5f, cosd, 0.5f);             // in [0,1]
            float q2 = b * b;                             // ^2
            q2 *= q2;                                     // ^4
            q2 *= q2;                                     // ^8
            q2 *= q2;                                     // ^16
            q2 *= q2;                                     // ^32
            float g = 2.0f * q2;

            float4 f20 = *reinterpret_cast<const float4*>(&f2sh[p][0]);
            float4 f21 = *reinterpret_cast<const float4*>(&f2sh[p][4]);
            float4* dst = reinterpret_cast<float4*>(o + 384 + (m << 3));
            dst[0] = make_float4(g * f20.x, g * f20.y, g * f20.z, g * f20.w);
            dst[1] = make_float4(g * f21.x, g * f21.y, g * f21.z, g * f21.w);
        }
    }
}

extern "C" void kernel_launch(void* const* d_in, const int* in_sizes, int n_in,
                              void* d_out, int out_size)
{
    const float* coeff = (const float*)d_in[0];
    float* out = (float*)d_out;
    orbital_aev_kernel<<<NBLOCKS, 128>>>(coeff, out);
}

// round 5
// speedup vs baseline: 1.0673x; 1.0673x over previous
#include <cuda_runtime.h>

// OrbitalAEVComputer: coefficients [64,256,45] f32 -> out [64,256,4608] f32
// Per (conf,atom): 12 AOVs (4 p + 8 reordered d), radial 12*32, angular 66*8*8.

#define NBLOCKS (64 * 256)
#define OUT_STRIDE 4608
#define NPAIR 66

// cos/sin of shfZ = linspace(0.19634954, 2.94524311, 8)  (odd multiples of pi/16)
__constant__ float COSZ[8] = {
     0.98078528f,  0.83146961f,  0.55557023f,  0.19509032f,
    -0.19509032f, -0.55557023f, -0.83146961f, -0.98078528f
};
__constant__ float SINZ[8] = {
     0.19509032f,  0.55557023f,  0.83146961f,  0.98078528f,
     0.98078528f,  0.83146961f,  0.55557023f,  0.19509032f
};

// triu_indices(12, k=1), i-major
__constant__ unsigned char IU[NPAIR] = {
    0,0,0,0,0,0,0,0,0,0,0,
    1,1,1,1,1,1,1,1,1,1,
    2,2,2,2,2,2,2,2,2,
    3,3,3,3,3,3,3,3,
    4,4,4,4,4,4,4,
    5,5,5,5,5,5,
    6,6,6,6,6,
    7,7,7,7,
    8,8,8,
    9,9,
    10
};
__constant__ unsigned char JU[NPAIR] = {
    1,2,3,4,5,6,7,8,9,10,11,
    2,3,4,5,6,7,8,9,10,11,
    3,4,5,6,7,8,9,10,11,
    4,5,6,7,8,9,10,11,
    5,6,7,8,9,10,11,
    6,7,8,9,10,11,
    7,8,9,10,11,
    8,9,10,11,
    9,10,11,
    10,11,
    11
};

__global__ __launch_bounds__(128, 8)
void orbital_aev_kernel(const float* __restrict__ coeff, float* __restrict__ out)
{
    __shared__ float  dsh[12];
    __shared__ float  nvsh[12][3];
    __shared__ float4 pairsh[NPAIR];   // (cz = 0.95*cos, sz = sqrt(1-cz^2), avdist, 0)

    const int t = threadIdx.x;
    const float* __restrict__ c = coeff + (size_t)blockIdx.x * 45;
    float* __restrict__ o = out + (size_t)blockIdx.x * OUT_STRIDE;

    // ---- Build 12 AOVs: dist + normalized vectors into SMEM ----
    if (t < 12) {
        float x, y, z;
        if (t < 4) {
            int b = 9 + 3 * t;
            x = c[b]; y = c[b + 1]; z = c[b + 2];
        } else {
            int r = (t - 4) >> 1;
            int b = 21 + 6 * r;
            if (((t - 4) & 1) == 0) {        // d row picks [0,2,5]
                x = c[b];     y = c[b + 2]; z = c[b + 5];
            } else {                          // then [4,3,1]
                x = c[b + 4]; y = c[b + 3]; z = c[b + 1];
            }
        }
        float s = x * x + y * y + z * z;
        float inv, d;
        if (s > 1e-24f) { inv = rsqrtf(s); d = s * inv; }
        else            { inv = 0.0f;      d = 0.0f;    }
        dsh[t] = d;
        nvsh[t][0] = x * inv;
        nvsh[t][1] = y * inv;
        nvsh[t][2] = z * inv;
    }
    __syncthreads();

    // ---- Pair terms: cz = 0.95*cos(angle), sz = sqrt(1-cz^2), av = mean dist ----
    if (t < NPAIR) {
        int i = IU[t], j = JU[t];
        float cc = nvsh[i][0] * nvsh[j][0]
                 + nvsh[i][1] * nvsh[j][1]
                 + nvsh[i][2] * nvsh[j][2];
        float cz = 0.95f * cc;
        float sz = sqrtf(fmaxf(0.0f, 1.0f - cz * cz));
        float av = 0.5f * (dsh[i] + dsh[j]);
        pairsh[t] = make_float4(cz, sz, av, 0.0f);
    }

    // ---- Radial: s_aev == r_aev (identical shifts & eta). 384 outputs as 96 STG.128.
    if (t < 96) {
        int aov = t >> 3;
        int q   = t & 7;
        float d  = dsh[aov];
        int   kb = (q & 3) << 2;
        float u0 = d - (0.5f + 0.2f * (float)(kb + 0));
        float u1 = d - (0.5f + 0.2f * (float)(kb + 1));
        float u2 = d - (0.5f + 0.2f * (float)(kb + 2));
        float u3 = d - (0.5f + 0.2f * (float)(kb + 3));
        float4 v = make_float4(__expf(-16.0f * u0 * u0),
                               __expf(-16.0f * u1 * u1),
                               __expf(-16.0f * u2 * u2),
                               __expf(-16.0f * u3 * u3));
        *reinterpret_cast<float4*>(o + (aov << 5) + (q << 2)) = v;
    }
    __syncthreads();

    // ---- Angular: 528 tasks (pair p, z = t&7). Each task computes its own 8 f2 values
    //      (MUFU is cheap; no shuffles / no smem table / no extra barrier). ----
    const float cosz = COSZ[t & 7];
    const float sinz = SINZ[t & 7];
    #pragma unroll
    for (int iter = 0; iter < 5; iter++) {
        int m = t + 128 * iter;
        if (m < 528) {
            int p = m >> 3;
            float4 cs = pairsh[p];                        // broadcast LDS.128 within group

            // factor1: cos(angle - shfZ) = cz*cosZ + sqrt(1-cz^2)*sinZ (exact identity)
            float cosd = fmaf(cs.x, cosz, cs.y * sinz);
            float b = fmaf(0.5f, cosd, 0.5f);             // (1+cosd)/2 in [0,1]
            float q2 = b * b;                             // ^2
            q2 *= q2;                                     // ^4
            q2 *= q2;                                     // ^8
            q2 *= q2;                                     // ^16
            q2 *= q2;                                     // ^32
            float g = 2.0f * q2;

            // factor2 for all 8 shfA = 0.5 + (3/7)*a
            float av = cs.z;
            float f2v[8];
            #pragma unroll
            for (int a = 0; a < 8; a++) {
                float ua = av - (0.5f + (3.0f / 7.0f) * (float)a);
                f2v[a] = __expf(-8.0f * ua * ua);
            }

            float4* dst = reinterpret_cast<float4*>(o + 384 + (m << 3));
            dst[0] = make_float4(g * f2v[0], g * f2v[1], g * f2v[2], g * f2v[3]);
            dst[1] = make_float4(g * f2v[4], g * f2v[5], g * f2v[6], g * f2v[7]);
        }
    }
}

extern "C" void kernel_launch(void* const* d_in, const int* in_sizes, int n_in,
                              void* d_out, int out_size)
{
    const float* coeff = (const float*)d_in[0];
    float* out = (float*)d_out;
    orbital_aev_kernel<<<NBLOCKS, 128>>>(coeff, out);
}